// round 7
// baseline (speedup 1.0000x reference)
#include <cuda_runtime.h>

#define BB 128
#define HH 256
#define WW 256
#define SHIFT 32
#define HW (HH*WW)      // 65536
#define CHW (3*HW)      // 196608
#define RBLKS 32        // reduce blocks per image
#define BPI 64          // transform blocks per image
#define QTR (BB/4)      // 32 images per pipeline chunk

__device__ float g_part[BB * RBLKS];

// ---- reduce role: one block sums 1/32 of one image, writes one partial ----
__device__ __forceinline__ void reduce_role(const float* __restrict__ imgs,
                                            int b, int blk)
{
    const float4* p = (const float4*)(imgs + (size_t)b * CHW);
    const int per_blk = (CHW / 4) / RBLKS;   // 1536 float4
    int base = blk * per_blk;
    float s0 = 0.f, s1 = 0.f;
    #pragma unroll
    for (int i = 0; i < 6; i += 2) {         // front-batched, 2 accumulators
        float4 va = p[base + i * 256 + threadIdx.x];
        float4 vb = p[base + (i + 1) * 256 + threadIdx.x];
        s0 += (va.x + va.y) + (va.z + va.w);
        s1 += (vb.x + vb.y) + (vb.z + vb.w);
    }
    float s = s0 + s1;
    #pragma unroll
    for (int o = 16; o; o >>= 1) s += __shfl_down_sync(0xffffffffu, s, o);
    __shared__ float ss[8];
    if ((threadIdx.x & 31) == 0) ss[threadIdx.x >> 5] = s;
    __syncthreads();
    if (threadIdx.x < 8) {
        s = ss[threadIdx.x];
        #pragma unroll
        for (int o = 4; o; o >>= 1) s += __shfl_down_sync(0xffu, s, o);
        if (threadIdx.x == 0) g_part[b * RBLKS + blk] = s;
    }
}

// ---- transform role: one float4 per thread in each of 3 planes ----
__device__ __forceinline__ void transform_role(
    const float* __restrict__ imgs,
    const float* __restrict__ br,  const float* __restrict__ sat,
    const float* __restrict__ con, const int* __restrict__ tx,
    const int* __restrict__ ty,    const int* __restrict__ cx,
    const int* __restrict__ cy,    float* __restrict__ out,
    int b, int blk)
{
    int idx4 = blk * 256 + threadIdx.x;               // float4 index in plane
    int h    = idx4 >> 6;                             // 64 float4 per row
    int w0   = (idx4 & 63) << 2;

    // One warp sums this image's 32 partials (L2-broadcast hits).
    __shared__ float sM0;
    if (threadIdx.x < 32) {
        float s = g_part[b * RBLKS + threadIdx.x];
        #pragma unroll
        for (int o = 16; o; o >>= 1) s += __shfl_down_sync(0xffffffffu, s, o);
        if (threadIdx.x == 0) sM0 = s * (1.0f / (float)CHW);
    }
    __syncthreads();

    // out = Af*v + Bf*channel_mean + Cf on valid pixels, else 0
    float a  = sat[b] * 2.0f;
    float k  = con[b] + 0.5f;
    float Af = k * a;
    float Bf = k * (1.0f - a);
    float Cf = (1.0f - k) * sM0 + (br[b] - 0.5f);

    int txs = tx[b] - SHIFT;
    int tys = ty[b] - SHIFT;
    int cxv = cx[b], cyv = cy[b];
    int xlo = max(0, cxv - 64), xhi = min(HH - 1, cxv + 63);
    int ylo = max(0, cyv - 64), yhi = min(WW - 1, cyv + 63);

    int  sh       = h + txs;
    bool rowvalid = (sh >= 0) & (sh < HH);
    bool rowcut   = (h >= xlo) & (h <= xhi);
    int  sh_c     = min(max(sh, 0), HH - 1);          // safe address even when invalid

    const float* src = imgs + (size_t)b * CHW + (size_t)sh_c * WW;

    float o0[4], o1[4], o2[4];
    #pragma unroll
    for (int j = 0; j < 4; j++) {
        int  w  = w0 + j;
        int  sw = w + tys;
        bool valid = rowvalid & (sw >= 0) & (sw < WW)
                   & !(rowcut & (w >= ylo) & (w <= yhi));
        int sw_c = min(max(sw, 0), WW - 1);
        if (valid) {
            // last-use reads: this chunk's input dies after this kernel
            float v0 = __ldcs(src + sw_c);
            float v1 = __ldcs(src + HW + sw_c);
            float v2 = __ldcs(src + 2 * HW + sw_c);
            float m  = (v0 + v1 + v2) * (1.0f / 3.0f);
            float bm = fmaf(Bf, m, Cf);
            o0[j] = fmaf(Af, v0, bm);
            o1[j] = fmaf(Af, v1, bm);
            o2[j] = fmaf(Af, v2, bm);
        } else {
            o0[j] = 0.f; o1[j] = 0.f; o2[j] = 0.f;
        }
    }

    float* dst = out + (size_t)b * CHW + (size_t)h * WW + w0;
    __stcs((float4*)(dst),          make_float4(o0[0], o0[1], o0[2], o0[3]));
    __stcs((float4*)(dst + HW),     make_float4(o1[0], o1[1], o1[2], o1[3]));
    __stcs((float4*)(dst + 2 * HW), make_float4(o2[0], o2[1], o2[2], o2[3]));
}

// Mixed kernel: FIRST nred*RBLKS blocks reduce images [rbase, rbase+nred)
// (dispatched earliest so the next stage's dependency completes ASAP),
// remaining ntr*BPI blocks transform images [tbase, tbase+ntr).
// The inter-launch barrier provides the reduce->transform ordering.
__global__ void __launch_bounds__(256) fused_kernel(
    const float* __restrict__ imgs,
    const float* __restrict__ br,  const float* __restrict__ sat,
    const float* __restrict__ con, const int* __restrict__ tx,
    const int* __restrict__ ty,    const int* __restrict__ cx,
    const int* __restrict__ cy,    float* __restrict__ out,
    int tbase, int ntr, int rbase, int nred)
{
    int nredblk = nred * RBLKS;
    if ((int)blockIdx.x < nredblk) {
        reduce_role(imgs, rbase + blockIdx.x / RBLKS, blockIdx.x % RBLKS);
    } else {
        int tix = blockIdx.x - nredblk;
        transform_role(imgs, br, sat, con, tx, ty, cx, cy, out,
                       tbase + tix / BPI, tix % BPI);
    }
}

extern "C" void kernel_launch(void* const* d_in, const int* in_sizes, int n_in,
                              void* d_out, int out_size)
{
    const float* imgs = (const float*)d_in[0];
    const float* br   = (const float*)d_in[1];
    const float* sat  = (const float*)d_in[2];
    const float* con  = (const float*)d_in[3];
    const int*   tx   = (const int*)d_in[4];
    const int*   ty   = (const int*)d_in[5];
    const int*   cx   = (const int*)d_in[6];
    const int*   cy   = (const int*)d_in[7];
    float*       out  = (float*)d_out;

    const int RB = QTR * RBLKS;   // 1024 reduce blocks per chunk
    const int TB = QTR * BPI;     // 2048 transform blocks per chunk

    // K0: reduce q0
    fused_kernel<<<RB, 256>>>(imgs, br, sat, con, tx, ty, cx, cy, out,
                              0, 0, 0 * QTR, QTR);
    // K1..K3: reduce q(i+1) + transform q(i)
    fused_kernel<<<RB + TB, 256>>>(imgs, br, sat, con, tx, ty, cx, cy, out,
                              0 * QTR, QTR, 1 * QTR, QTR);
    fused_kernel<<<RB + TB, 256>>>(imgs, br, sat, con, tx, ty, cx, cy, out,
                              1 * QTR, QTR, 2 * QTR, QTR);
    fused_kernel<<<RB + TB, 256>>>(imgs, br, sat, con, tx, ty, cx, cy, out,
                              2 * QTR, QTR, 3 * QTR, QTR);
    // K4: transform q3
    fused_kernel<<<TB, 256>>>(imgs, br, sat, con, tx, ty, cx, cy, out,
                              3 * QTR, QTR, 0, 0);
}